// round 3
// baseline (speedup 1.0000x reference)
#include <cuda_runtime.h>
#include <math.h>

// DTW on 2048x2048 cost matrix, anti-diagonal wavefront, single CTA.
// Each thread owns RPT consecutive rows; diag d-1 / d-2 values live in
// registers. Cross-thread (row) communication: shfl.up within warp,
// double-buffered smem slot across warp boundaries (1 barrier / diagonal).
// Out-of-range columns are handled by padding y with 1e19 so invalid cells
// self-poison to huge values (no per-cell predication).

#define LEN   2048
#define NT    512
#define RPT   4                 // rows per thread: NT*RPT == LEN
#define NW    (NT / 32)
#define BIGV  1e19f
#define OFF   2046              // ypad index offset: j in [-2046, 4095]
#define YPSZ  6144

__global__ __launch_bounds__(NT, 1)
void dtw_wavefront(const float* __restrict__ x,
                   const float* __restrict__ y,
                   float* __restrict__ out)
{
    __shared__ float  ypad[YPSZ];
    __shared__ float2 bdry[2][NW];   // double-buffered warp-boundary (b,a)

    const int tid  = threadIdx.x;
    const int lane = tid & 31;
    const int warp = tid >> 5;

    // Fill padded y: valid columns hold y[j], everything else holds BIGV so
    // (x - BIGV)^2 ~ 1e38 poisons out-of-range cells automatically.
    for (int idx = tid; idx < YPSZ; idx += NT) {
        int j = idx - OFF;
        ypad[idx] = (j >= 0 && j < LEN) ? y[j] : BIGV;
    }
    __syncthreads();

    const int r0 = tid * RPT;

    // x values for this thread's rows (fixed for the whole kernel).
    float xs[RPT];
#pragma unroll
    for (int k = 0; k < RPT; k++) xs[k] = x[r0 + k];

    // State after diagonal 0: only cell (0,0) is finite.
    float b[RPT], a[RPT];
#pragma unroll
    for (int k = 0; k < RPT; k++) { b[k] = BIGV; a[k] = BIGV; }
    if (tid == 0) {
        float c00 = xs[0] - ypad[OFF];       // x[0] - y[0]
        b[0] = c00 * c00;                    // DTW[0][0]
    }

    // y register cache: yv[k] = y[d - r0 - k] for the previous diagonal (d=0).
    float yv[RPT];
#pragma unroll
    for (int k = 0; k < RPT; k++) yv[k] = ypad[OFF - r0 - k];

    // Carry-in for lane 0: neighbor warp's last-row (b, a). Warp 0 row -1 = BIG.
    float cb = BIGV, ca = BIGV;

    const float* yp = &ypad[OFF + 1 - r0];   // y[d - r0] pointer, d starts at 1

    for (int d = 1; d <= 2 * LEN - 2; d++) {
        // Shift y window down one column; one new shared load per thread.
        float ynew = *yp++;
        float ycur[RPT];
        ycur[0] = ynew;
#pragma unroll
        for (int k = 1; k < RPT; k++) ycur[k] = yv[k - 1];

        // Neighbor thread's bottom-row values at diag d-1 (b) and d-2 (a).
        float nb_b = __shfl_up_sync(0xffffffffu, b[RPT - 1], 1);
        float nb_a = __shfl_up_sync(0xffffffffu, a[RPT - 1], 1);
        if (lane == 0) { nb_b = cb; nb_a = ca; }

        // RPT independent cells (all inputs are from diagonals d-1 / d-2).
        float n[RPT];
#pragma unroll
        for (int k = 0; k < RPT; k++) {
            float up   = (k == 0) ? nb_b : b[k - 1];
            float dg   = (k == 0) ? nb_a : a[k - 1];
            float left = b[k];
            float c    = xs[k] - ycur[k];
            float m    = fminf(fminf(up, left), dg);
            n[k] = fmaf(c, c, m);
        }

        // Rotate state.
#pragma unroll
        for (int k = 0; k < RPT; k++) { a[k] = b[k]; b[k] = n[k]; }
#pragma unroll
        for (int k = 0; k < RPT; k++) yv[k] = ycur[k];

        // Publish warp-boundary values (double-buffered), one barrier/diag.
        const int par = d & 1;
        if (lane == 31) bdry[par][warp] = make_float2(b[RPT - 1], a[RPT - 1]);
        __syncthreads();
        if (lane == 0 && warp > 0) {
            float2 v = bdry[par][warp - 1];
            cb = v.x; ca = v.y;
        }
    }

    // Final cell: row 2047 on diagonal 4094 -> thread NT-1, slot RPT-1.
    if (tid == NT - 1) out[0] = sqrtf(b[RPT - 1]);
}

extern "C" void kernel_launch(void* const* d_in, const int* in_sizes, int n_in,
                              void* d_out, int out_size)
{
    const float* x = (const float*)d_in[0];
    const float* y = (const float*)d_in[1];
    float* out = (float*)d_out;
    (void)in_sizes; (void)n_in; (void)out_size;
    dtw_wavefront<<<1, NT>>>(x, y, out);
}

// round 4
// speedup vs baseline: 1.3343x; 1.3343x over previous
#include <cuda_runtime.h>
#include <math.h>

// DTW 2048x2048, single CTA, warp-skewed anti-diagonal block pipeline.
//
// 128 threads, each owns RPT=16 consecutive rows (state for diag d-1 in b[],
// d-2 in a[], registers only). Diagonals are processed in blocks of B=16:
// warp w processes block q at step s = q + w (1-block skew), so the only
// CTA-wide barrier is per *block*, not per diagonal. Intra-warp row handoff
// stays shfl-per-diagonal; cross-warp handoff is B bottom-row values through
// a double-buffered smem array, written by lane 31, consumed by lane 0 of
// the warp below one step later.
//
// Out-of-range columns are handled by padding y with BIGV so invalid cells
// self-poison (no per-cell predication). Block body is fully unrolled with
// descending-k in-place updates => zero rotation MOVs.

#define LEN    2048
#define NT     128
#define NW     4                 // warps
#define RPT    16                // rows per thread (NT*RPT == LEN)
#define BD     16                // diagonals per block
#define NBLK   256               // blocks cover d = 1..4096 (>= 4094)
#define NSTEPS (NBLK + NW - 1)
#define BIGV   1e19f
#define OFF    2047
#define YPSZ   6144

__global__ __launch_bounds__(NT, 1)
void dtw_wavefront(const float* __restrict__ x,
                   const float* __restrict__ y,
                   float* __restrict__ out)
{
    __shared__ float  ypad[YPSZ];
    __shared__ float4 bdry[2][NW + 1][BD / 4];  // [parity][producer row][diag/4]

    const int tid  = threadIdx.x;
    const int lane = tid & 31;
    const int warp = tid >> 5;

    // Padded y: valid columns hold y[j], outside holds BIGV (cell poisoning).
    for (int idx = tid; idx < YPSZ; idx += NT) {
        int j = idx - OFF;
        ypad[idx] = (j >= 0 && j < LEN) ? y[j] : BIGV;
    }
    // Warp 0 reads boundary row 0: preset to BIGV (both parities), never written.
    if (tid < 2 * (BD / 4)) {
        int p = tid / (BD / 4), c = tid % (BD / 4);
        bdry[p][0][c] = make_float4(BIGV, BIGV, BIGV, BIGV);
    }
    __syncthreads();

    const int r0 = tid * RPT;

    float xs[RPT];
#pragma unroll
    for (int k = 0; k < RPT; k++) xs[k] = x[r0 + k];

    // State after diagonal 0: only cell (0,0) finite.
    float b[RPT], a[RPT];
#pragma unroll
    for (int k = 0; k < RPT; k++) { b[k] = BIGV; a[k] = BIGV; }
    if (tid == 0) {
        float c00 = xs[0] - ypad[OFF];
        b[0] = c00 * c00;
    }

    // lane-0 carries: neighbor-warp bottom-row b at (block start - 1), (- 2).
    float cb = BIGV, ca = BIGV;

    for (int s = 0; s < NSTEPS; s++) {
        const int q = s - warp;
        if (q >= 0 && q < NBLK) {
            const int wpar = s & 1;
            const int rpar = wpar ^ 1;
            const int d0   = 1 + q * BD;

            // Boundary values from warp above: e[i] = its bottom b at diag d0+i.
            float e[BD];
            {
                const float4* src = bdry[rpar][warp];
#pragma unroll
                for (int c4 = 0; c4 < BD / 4; c4++) {
                    float4 v = src[c4];
                    e[c4 * 4 + 0] = v.x; e[c4 * 4 + 1] = v.y;
                    e[c4 * 4 + 2] = v.z; e[c4 * 4 + 3] = v.w;
                }
            }

            // y window for the whole block: cell (i,k) uses yblk[16 + i - k].
            // Base index OFF + d0 - r0 - 16 = 2032 + 16*(q - tid): float4-aligned,
            // and always within [0, YPSZ-32].
            float yblk[32];
            {
                const float4* yp4 =
                    reinterpret_cast<const float4*>(&ypad[OFF + d0 - r0 - 16]);
#pragma unroll
                for (int c4 = 0; c4 < 8; c4++) {
                    float4 v = yp4[c4];
                    yblk[c4 * 4 + 0] = v.x; yblk[c4 * 4 + 1] = v.y;
                    yblk[c4 * 4 + 2] = v.z; yblk[c4 * 4 + 3] = v.w;
                }
            }

            float* bp = (float*)bdry[wpar][warp + 1];   // publish target
            const bool isl0  = (lane == 0);
            const bool isl31 = (lane == 31);

            // nb_prev = neighbor thread's bottom b at d0-2 (current a[RPT-1]).
            float nb_prev = __shfl_up_sync(0xffffffffu, a[RPT - 1], 1);

#pragma unroll
            for (int i = 0; i < BD; i++) {
                // Neighbor bottom b at diag d0+i-1 (b[] still holds d-1 values).
                float nbb = __shfl_up_sync(0xffffffffu, b[RPT - 1], 1);
                float up0 = isl0 ? ((i >= 1) ? e[i - 1] : cb) : nbb;
                float dg0 = isl0 ? ((i >= 2) ? e[i - 2] : ((i == 1) ? cb : ca))
                                 : nb_prev;
                nb_prev = nbb;

                // Descending k: in-place update, reads only untouched old state.
#pragma unroll
                for (int k = RPT - 1; k >= 0; k--) {
                    float up = (k == 0) ? up0 : b[k - 1];
                    float dg = (k == 0) ? dg0 : a[k - 1];
                    float c  = xs[k] - yblk[16 + i - k];
                    float m  = fminf(fminf(up, b[k]), dg);
                    a[k] = b[k];
                    b[k] = fmaf(c, c, m);
                }

                // Publish bottom-row value for the warp below.
                if (isl31) bp[i] = b[RPT - 1];

                // Final cell (2047, 2047) lives at d = 4094 = (1 + 255*16) + 13.
                if (i == 13) {
                    if (q == NBLK - 1 && tid == NT - 1)
                        out[0] = sqrtf(b[RPT - 1]);
                }
            }

            // Carries for next block: last two boundary diags of this block.
            ca = e[BD - 2];
            cb = e[BD - 1];
        }
        __syncthreads();
    }
}

extern "C" void kernel_launch(void* const* d_in, const int* in_sizes, int n_in,
                              void* d_out, int out_size)
{
    const float* x = (const float*)d_in[0];
    const float* y = (const float*)d_in[1];
    float* out = (float*)d_out;
    (void)in_sizes; (void)n_in; (void)out_size;
    dtw_wavefront<<<1, NT>>>(x, y, out);
}

// round 6
// speedup vs baseline: 1.5299x; 1.1466x over previous
#include <cuda_runtime.h>
#include <math.h>

// DTW 2048x2048, 4-CTA x 4-warp skewed anti-diagonal block pipeline.
//
// Thread t of CTA c owns rows r0 = c*512 + t*4 .. +3; diag d-1 / d-2 values
// live in registers (b[]/a[], roles alternating per diagonal => no rotation
// MOVs). Diagonals are processed in blocks of BD=32. Pipeline stage of
// (cta c, warp w) = 5c + w: warp w handles block q at step s = q + stage.
// Intra-CTA handoff: double-buffered smem rows (lane31 -> lane0 of next
// warp). Inter-CTA handoff: global scratch + release/acquire flag through
// L2 (2-step slack covers the cross-SM latency). Flags are zeroed by a
// pre-kernel each launch, keeping replays deterministic.
//
// Out-of-range columns are poisoned via y-padding with BIGV (no per-cell
// predication); inf saturation is harmless because every valid cell always
// has at least one valid predecessor.

#define LEN    2048
#define C      4
#define NT     128
#define NW     4
#define RPT    4                  // C*NT*RPT == LEN
#define BD     32                 // diagonals per block
#define NBLK   128                // covers d = 1..4096 (>= 4094)
#define NSTAGE ((C - 1) * (NW + 1) + (NW - 1))   // 18
#define NSTEPS (NBLK + NSTAGE)                   // 146
#define BIGV   1e19f
#define OFF    2047
#define YPSZ   6144

__device__ float g_bound[C][NBLK][BD];
__device__ int   g_flag[C][NBLK];

__global__ void reset_flags_kernel()
{
    int i = threadIdx.x;
    if (i < C * NBLK) ((int*)g_flag)[i] = 0;
}

__global__ __launch_bounds__(NT, 1)
void dtw_wavefront(const float* __restrict__ x,
                   const float* __restrict__ y,
                   float* __restrict__ out)
{
    __shared__ float ypad[YPSZ];
    __shared__ float bdry[2][NW][BD];   // [parity][consumer warp][diag]

    const int tid  = threadIdx.x;
    const int lane = tid & 31;
    const int warp = tid >> 5;
    const int cta  = blockIdx.x;

    for (int idx = tid; idx < YPSZ; idx += NT) {
        int j = idx - OFF;
        ypad[idx] = (j >= 0 && j < LEN) ? y[j] : BIGV;
    }
    __syncthreads();

    const int r0 = cta * (NT * RPT) + tid * RPT;

    float xs[RPT];
#pragma unroll
    for (int k = 0; k < RPT; k++) xs[k] = x[r0 + k];

    // State: b = diag d0-1, a = diag d0-2. Only (0,0) finite after diag 0.
    float b[RPT], a[RPT];
#pragma unroll
    for (int k = 0; k < RPT; k++) { b[k] = BIGV; a[k] = BIGV; }
    if (cta == 0 && tid == 0) {
        float c00 = xs[0] - ypad[OFF];
        b[0] = c00 * c00;
    }

    float cb = BIGV, ca = BIGV;     // lane0 carries: upstream bottom b at d0-1, d0-2
    const int  stage = cta * (NW + 1) + warp;
    const bool isl0  = (lane == 0);
    const bool isl31 = (lane == 31);
    const bool wlast = (cta == C - 1 && tid == NT - 1);

    for (int s = 0; s < NSTEPS; s++) {
        const int q = s - stage;
        if (q >= 0 && q < NBLK) {
            const int wpar  = s & 1;
            const int rpar  = wpar ^ 1;
            const int d0    = 1 + q * BD;
            const bool qlast = (q == NBLK - 1);

            // ---- fetch upstream boundary e[i] = bottom-row b at diag d0+i ----
            float e[BD];
            if (warp == 0) {
                if (cta == 0) {
#pragma unroll
                    for (int i = 0; i < BD; i++) e[i] = BIGV;
                } else {
                    if (isl0) {
                        while (*(volatile int*)&g_flag[cta - 1][q] == 0)
                            __nanosleep(32);
                    }
                    __syncwarp();
                    __threadfence();
                    const float4* gp =
                        (const float4*)&g_bound[cta - 1][q][0];
#pragma unroll
                    for (int c4 = 0; c4 < BD / 4; c4++) {
                        float4 v = __ldcg(gp + c4);
                        e[c4 * 4 + 0] = v.x; e[c4 * 4 + 1] = v.y;
                        e[c4 * 4 + 2] = v.z; e[c4 * 4 + 3] = v.w;
                    }
                }
            } else {
                const float4* sp = (const float4*)&bdry[rpar][warp][0];
#pragma unroll
                for (int c4 = 0; c4 < BD / 4; c4++) {
                    float4 v = sp[c4];
                    e[c4 * 4 + 0] = v.x; e[c4 * 4 + 1] = v.y;
                    e[c4 * 4 + 2] = v.z; e[c4 * 4 + 3] = v.w;
                }
            }

            // ---- y window: cell (i,k) uses yblk[4 + i - k] ----
            float yblk[BD + RPT];
            {
                const float4* yp4 =
                    (const float4*)&ypad[OFF + d0 - r0 - RPT];
#pragma unroll
                for (int c4 = 0; c4 < (BD + RPT) / 4; c4++) {
                    float4 v = yp4[c4];
                    yblk[c4 * 4 + 0] = v.x; yblk[c4 * 4 + 1] = v.y;
                    yblk[c4 * 4 + 2] = v.z; yblk[c4 * 4 + 3] = v.w;
                }
            }

            // ---- publish target for lane31 ----
            float* bp;
            if (warp < NW - 1)       bp = &bdry[wpar][warp + 1][0];
            else if (cta < C - 1)    bp = &g_bound[cta][q][0];
            else                     bp = &bdry[wpar][0][0];   // dummy sink

            // neighbor thread's bottom b at d0-2
            float nb_prev = __shfl_up_sync(0xffffffffu, a[RPT - 1], 1);

            // ---- BD diagonals, roles of (P=d-1, Q=d-2->d) alternate ----
#define DIAG_STEP(I, P, Q) do {                                            \
            float nbb = __shfl_up_sync(0xffffffffu, P[RPT - 1], 1);        \
            float up0 = isl0 ? ((I) >= 1 ? e[(I) - 1] : cb) : nbb;         \
            float dg0 = isl0 ? ((I) >= 2 ? e[(I) - 2]                      \
                                         : ((I) == 1 ? cb : ca))           \
                             : nb_prev;                                    \
            nb_prev = nbb;                                                 \
            _Pragma("unroll")                                              \
            for (int k = RPT - 1; k >= 0; k--) {                           \
                float up = (k == 0) ? up0 : P[k - 1];                      \
                float dg = (k == 0) ? dg0 : Q[k - 1];                      \
                float cc = xs[k] - yblk[RPT + (I) - k];                    \
                Q[k] = fmaf(cc, cc, fminf(fminf(up, P[k]), dg));           \
            }                                                              \
            if (isl31) bp[(I)] = Q[RPT - 1];                               \
            if ((I) == 29) {                                               \
                if (qlast && wlast) out[0] = sqrtf(Q[RPT - 1]);            \
            }                                                              \
        } while (0)

#define DIAG_PAIR(I) DIAG_STEP(I, b, a); DIAG_STEP((I) + 1, a, b)

            DIAG_PAIR(0);  DIAG_PAIR(2);  DIAG_PAIR(4);  DIAG_PAIR(6);
            DIAG_PAIR(8);  DIAG_PAIR(10); DIAG_PAIR(12); DIAG_PAIR(14);
            DIAG_PAIR(16); DIAG_PAIR(18); DIAG_PAIR(20); DIAG_PAIR(22);
            DIAG_PAIR(24); DIAG_PAIR(26); DIAG_PAIR(28); DIAG_PAIR(30);

#undef DIAG_PAIR
#undef DIAG_STEP

            // carries for next block: upstream bottom at d0+BD-1, d0+BD-2
            ca = e[BD - 2];
            cb = e[BD - 1];

            // release flag for downstream CTA
            if (warp == NW - 1 && cta < C - 1 && isl31) {
                __threadfence();
                *(volatile int*)&g_flag[cta][q] = 1;
            }
        }
        __syncthreads();
    }
}

extern "C" void kernel_launch(void* const* d_in, const int* in_sizes, int n_in,
                              void* d_out, int out_size)
{
    const float* x = (const float*)d_in[0];
    const float* y = (const float*)d_in[1];
    float* out = (float*)d_out;
    (void)in_sizes; (void)n_in; (void)out_size;
    reset_flags_kernel<<<1, 512>>>();
    dtw_wavefront<<<C, NT>>>(x, y, out);
}

// round 11
// speedup vs baseline: 1.5845x; 1.0357x over previous
#include <cuda_runtime.h>
#include <math.h>

// DTW 2048x2048, 4-CTA x 4-warp skewed anti-diagonal block pipeline.
//
// R7 = R6 with the consumer poll made un-hoistable. R6's straggler re-poll
// used __ldcg in a do/while; __ldcg is not volatile, so the compiler could
// hoist the load and spin forever (the R6 container timeout). The poll now
// uses an asm-volatile ld.global.cg with a memory clobber + nanosleep.
//
// Design recap:
//  - Data-as-flag: producer (last warp of CTA c) writes boundary values
//    (all >= 0) straight to g_bound; g_bound is reset to -1 each launch by
//    a pre-kernel. Consumer validates per element -> no flag, no fence, no
//    poll round-trip ahead of the data load.
//  - One-block prefetch: at step s the consumer issues unchecked loads for
//    block q+1 (produced upstream at step s-1), computes block q, validates
//    next step. The L2 round-trip fully overlaps compute.
//  - Thread t of CTA c owns rows c*512 + t*4..+3 in registers, b[]/a[]
//    roles alternate per diagonal (no rotation MOVs), BD=32 diagonals per
//    block, stage(c,w) = 5c + w, intra-CTA handoff via double-buffered
//    smem, y padded with BIGV so out-of-range cells self-poison.

#define LEN    2048
#define C      4
#define NT     128
#define NW     4
#define RPT    4                  // C*NT*RPT == LEN
#define BD     32                 // diagonals per block
#define NBLK   128                // covers d = 1..4096 (>= 4094)
#define NSTAGE ((C - 1) * (NW + 1) + (NW - 1))   // 18
#define NSTEPS (NBLK + NSTAGE)                   // 146
#define BIGV   1e19f
#define SENT   -1.0f
#define OFF    2047
#define YPSZ   6144

__device__ float g_bound[C][NBLK][BD];

__global__ void reset_bound_kernel()
{
    int i = blockIdx.x * blockDim.x + threadIdx.x;
    if (i < C * NBLK * BD) ((float*)g_bound)[i] = SENT;
}

// Un-hoistable L2 load for the poll loop.
__device__ __forceinline__ float ld_cg_volatile(const float* p)
{
    float v;
    asm volatile("ld.global.cg.f32 %0, [%1];" : "=f"(v) : "l"(p) : "memory");
    return v;
}

__global__ __launch_bounds__(NT, 1)
void dtw_wavefront(const float* __restrict__ x,
                   const float* __restrict__ y,
                   float* __restrict__ out)
{
    __shared__ float ypad[YPSZ];
    __shared__ float bdry[2][NW][BD];   // [parity][consumer warp][diag]

    const int tid  = threadIdx.x;
    const int lane = tid & 31;
    const int warp = tid >> 5;
    const int cta  = blockIdx.x;

    for (int idx = tid; idx < YPSZ; idx += NT) {
        int j = idx - OFF;
        ypad[idx] = (j >= 0 && j < LEN) ? y[j] : BIGV;
    }
    __syncthreads();

    const int r0 = cta * (NT * RPT) + tid * RPT;

    float xs[RPT];
#pragma unroll
    for (int k = 0; k < RPT; k++) xs[k] = x[r0 + k];

    // State: b = diag d0-1, a = diag d0-2. Only (0,0) finite after diag 0.
    float b[RPT], a[RPT];
#pragma unroll
    for (int k = 0; k < RPT; k++) { b[k] = BIGV; a[k] = BIGV; }
    if (cta == 0 && tid == 0) {
        float c00 = xs[0] - ypad[OFF];
        b[0] = c00 * c00;
    }

    float cb = BIGV, ca = BIGV;     // lane0 carries: upstream bottom b at d0-1, d0-2
    const int  stage = cta * (NW + 1) + warp;
    const bool isl0  = (lane == 0);
    const bool isl31 = (lane == 31);
    const bool wlast = (cta == C - 1 && tid == NT - 1);
    const bool gcons = (warp == 0 && cta > 0);        // global consumer

    // Upstream boundary registers. For cta 0 / warp 0 these stay BIGV forever.
    float e[BD], en[BD];
#pragma unroll
    for (int i = 0; i < BD; i++) { e[i] = BIGV; en[i] = BIGV; }

    for (int s = 0; s < NSTEPS; s++) {
        const int q = s - stage;
        const bool active = (q >= 0 && q < NBLK);

        // ---- prefetch next block's global boundary (unchecked) ----
        if (gcons) {
            const int qn = q + 1;
            if (qn >= 0 && qn < NBLK) {
                const float4* gp = (const float4*)&g_bound[cta - 1][qn][0];
#pragma unroll
                for (int c4 = 0; c4 < BD / 4; c4++) {
                    float4 v = __ldcg(gp + c4);
                    en[c4 * 4 + 0] = v.x; en[c4 * 4 + 1] = v.y;
                    en[c4 * 4 + 2] = v.z; en[c4 * 4 + 3] = v.w;
                }
            }
        }

        if (active) {
            const int wpar  = s & 1;
            const int rpar  = wpar ^ 1;
            const int d0    = 1 + q * BD;
            const bool qlast = (q == NBLK - 1);

            // ---- obtain boundary e[i] = upstream bottom-row b at diag d0+i ----
            if (warp == 0) {
                if (cta > 0) {
                    // validate prefetched values; re-poll rare stragglers
                    const float* src = &g_bound[cta - 1][q][0];
#pragma unroll
                    for (int i = 0; i < BD; i++) {
                        if (e[i] < 0.0f) {
                            float v = ld_cg_volatile(src + i);
                            while (v < 0.0f) {
                                __nanosleep(20);
                                v = ld_cg_volatile(src + i);
                            }
                            e[i] = v;
                        }
                    }
                }
                // cta == 0: e stays BIGV
            } else {
                const float4* sp = (const float4*)&bdry[rpar][warp][0];
#pragma unroll
                for (int c4 = 0; c4 < BD / 4; c4++) {
                    float4 v = sp[c4];
                    e[c4 * 4 + 0] = v.x; e[c4 * 4 + 1] = v.y;
                    e[c4 * 4 + 2] = v.z; e[c4 * 4 + 3] = v.w;
                }
            }

            // ---- y window: cell (i,k) uses yblk[RPT + i - k] ----
            float yblk[BD + RPT];
            {
                const float4* yp4 = (const float4*)&ypad[OFF + d0 - r0 - RPT];
#pragma unroll
                for (int c4 = 0; c4 < (BD + RPT) / 4; c4++) {
                    float4 v = yp4[c4];
                    yblk[c4 * 4 + 0] = v.x; yblk[c4 * 4 + 1] = v.y;
                    yblk[c4 * 4 + 2] = v.z; yblk[c4 * 4 + 3] = v.w;
                }
            }

            // ---- publish target (generic volatile: smem or gmem) ----
            volatile float* bp;
            if (warp < NW - 1)       bp = &bdry[wpar][warp + 1][0];
            else if (cta < C - 1)    bp = &g_bound[cta][q][0];
            else                     bp = &bdry[wpar][0][0];   // dummy sink

            float nb_prev = __shfl_up_sync(0xffffffffu, a[RPT - 1], 1);

#define DIAG_STEP(I, P, Q) do {                                            \
            float nbb = __shfl_up_sync(0xffffffffu, P[RPT - 1], 1);        \
            float up0 = isl0 ? ((I) >= 1 ? e[(I) - 1] : cb) : nbb;         \
            float dg0 = isl0 ? ((I) >= 2 ? e[(I) - 2]                      \
                                         : ((I) == 1 ? cb : ca))           \
                             : nb_prev;                                    \
            nb_prev = nbb;                                                 \
            _Pragma("unroll")                                              \
            for (int k = RPT - 1; k >= 0; k--) {                           \
                float up = (k == 0) ? up0 : P[k - 1];                      \
                float dg = (k == 0) ? dg0 : Q[k - 1];                      \
                float cc = xs[k] - yblk[RPT + (I) - k];                    \
                Q[k] = fmaf(cc, cc, fminf(fminf(up, P[k]), dg));           \
            }                                                              \
            if (isl31) bp[(I)] = Q[RPT - 1];                               \
            if ((I) == 29) {                                               \
                if (qlast && wlast) out[0] = sqrtf(Q[RPT - 1]);            \
            }                                                              \
        } while (0)

#define DIAG_PAIR(I) DIAG_STEP(I, b, a); DIAG_STEP((I) + 1, a, b)

            DIAG_PAIR(0);  DIAG_PAIR(2);  DIAG_PAIR(4);  DIAG_PAIR(6);
            DIAG_PAIR(8);  DIAG_PAIR(10); DIAG_PAIR(12); DIAG_PAIR(14);
            DIAG_PAIR(16); DIAG_PAIR(18); DIAG_PAIR(20); DIAG_PAIR(22);
            DIAG_PAIR(24); DIAG_PAIR(26); DIAG_PAIR(28); DIAG_PAIR(30);

#undef DIAG_PAIR
#undef DIAG_STEP

            // carries for next block: upstream bottom at d0+BD-1, d0+BD-2
            ca = e[BD - 2];
            cb = e[BD - 1];
        }

        // rotate prefetch buffer (loads from this step have landed by now)
        if (gcons) {
#pragma unroll
            for (int i = 0; i < BD; i++) e[i] = en[i];
        }

        __syncthreads();
    }
}

extern "C" void kernel_launch(void* const* d_in, const int* in_sizes, int n_in,
                              void* d_out, int out_size)
{
    const float* x = (const float*)d_in[0];
    const float* y = (const float*)d_in[1];
    float* out = (float*)d_out;
    (void)in_sizes; (void)n_in; (void)out_size;
    reset_bound_kernel<<<32, 512>>>();
    dtw_wavefront<<<C, NT>>>(x, y, out);
}